// round 5
// baseline (speedup 1.0000x reference)
#include <cuda_runtime.h>
#include <math.h>

// Fixed shapes per reference
#define HH    112
#define WW    112
#define AA    9
#define NBOX  768          // B * 24
#define NCELL 3612672      // B*H*W*A
#define NF4   4515840      // total float4s in predictions
#define NTILE 28224        // NF4/160: warp tiles of 160 float4s (2560 B)

#define BLOCKS  1184
#define THREADS 256

__device__ float g_partials[BLOCKS];
__device__ int   g_counter = 0;   // zero-inited at module load; last block resets it

// Accurate softplus (tiny phase-2 tail only)
__device__ __forceinline__ float softplus_acc(float x) {
    return fmaxf(x, 0.0f) + log1pf(expf(-fabsf(x)));
}

// float4 with index f (f mod 5 = r) carries the obj element at component r-1
// when r != 0. Skip slots return -1e30 -> fmax gives 0, exp gives 0, so the
// softplus contribution is exactly 0.
__device__ __forceinline__ float pick_obj(float4 v, int r) {
    float x = (r == 1) ? v.x : (r == 2) ? v.y : (r == 3) ? v.z : v.w;
    return (r == 0) ? -1e30f : x;
}

__global__ __launch_bounds__(THREADS) void loss_kernel(const float* __restrict__ pred,
                                                       const float* __restrict__ bbox,
                                                       float* __restrict__ out) {
    // ---------- Phase 1: warp-cooperative coalesced scan of the obj channel ----------
    // Warp tile = 160 contiguous float4s. Lane l loads p4[base + 32k + l],
    // k=0..4: five coalesced LDG.128 (512B each, 4 wavefronts). Lane l's
    // float4 index residues are r_k = (l + 2k) mod 5 -> each residue once,
    // so every lane handles exactly 4 obj elements per tile.
    const float4* __restrict__ p4 = reinterpret_cast<const float4*>(pred);
    const int tid  = threadIdx.x;
    const int lane = tid & 31;
    const int wg   = (blockIdx.x * THREADS + tid) >> 5;   // global warp id
    const int nwg  = (gridDim.x * THREADS) >> 5;

    const int l5 = lane % 5;
    const int r0 = l5;
    const int r1 = (l5 + 2) % 5;
    const int r2 = (l5 + 4) % 5;
    const int r3 = (l5 + 1) % 5;
    const int r4 = (l5 + 3) % 5;

    float acc = 0.0f;
    for (int t = wg; t < NTILE; t += nwg) {
        int base = t * 160 + lane;
        float4 v0 = p4[base];
        float4 v1 = p4[base + 32];
        float4 v2 = p4[base + 64];
        float4 v3 = p4[base + 96];
        float4 v4 = p4[base + 128];

        float x0 = pick_obj(v0, r0);
        float x1 = pick_obj(v1, r1);
        float x2 = pick_obj(v2, r2);
        float x3 = pick_obj(v3, r3);
        float x4 = pick_obj(v4, r4);

        acc += fmaxf(x0, 0.0f) + fmaxf(x1, 0.0f) + fmaxf(x2, 0.0f)
             + fmaxf(x3, 0.0f) + fmaxf(x4, 0.0f);

        float e0 = expf(-fabsf(x0));
        float e1 = expf(-fabsf(x1));
        float e2 = expf(-fabsf(x2));
        float e3 = expf(-fabsf(x3));
        float e4 = expf(-fabsf(x4));
        // each term in [1,2], product <= 32: exact range, ~4 extra roundings
        float p  = (1.0f + e0) * (1.0f + e1);
        float q  = (1.0f + e2) * (1.0f + e3);
        acc += logf(p * q * (1.0f + e4));
    }

    __shared__ float s[THREADS];
    s[tid] = acc;
    __syncthreads();
    #pragma unroll
    for (int o = THREADS / 2; o > 0; o >>= 1) {
        if (tid < o) s[tid] += s[tid + o];
        __syncthreads();
    }

    __shared__ bool is_last;
    if (tid == 0) {
        g_partials[blockIdx.x] = s[0];
        __threadfence();
        int old = atomicAdd(&g_counter, 1);
        is_last = (old == (int)gridDim.x - 1);
    }
    __syncthreads();
    if (!is_last) return;

    // ---------- Phase 2: last block only — targets, dedup, gather, finalize ----------
    __shared__ int   s_key[NBOX];
    __shared__ float s_t[NBOX][4];

    // anchors computed in double on device (bit-identical to R1/R3/R4 passes)
    float aw[AA], ah[AA];
    {
        const double S[3] = {32.0, 64.0, 128.0};
        const double R[3] = {0.5, 1.0, 2.0};
        #pragma unroll
        for (int i = 0; i < AA; i++) {
            double sd = S[i / 3], rd = R[i % 3];
            aw[i] = (float)(sd * sqrt(rd) / 224.0);
            ah[i] = (float)(sd / sqrt(rd) / 224.0);
        }
    }

    for (int idx = tid; idx < NBOX; idx += THREADS) {
        float cx = bbox[idx * 4 + 0];
        float cy = bbox[idx * 4 + 1];
        float w  = bbox[idx * 4 + 2];
        float h  = bbox[idx * 4 + 3];
        bool valid = (cx != 0.0f) || (cy != 0.0f) || (w != 0.0f) || (h != 0.0f);
        if (!valid) { s_key[idx] = -1; continue; }

        int gx = (int)floorf(cx * (float)WW); gx = min(max(gx, 0), WW - 1);
        int gy = (int)floorf(cy * (float)HH); gy = min(max(gy, 0), HH - 1);

        float wh = w * h;
        int best = 0; float bi = -1e30f;
        #pragma unroll
        for (int a = 0; a < AA; a++) {
            float inter = fminf(w, aw[a]) * fminf(h, ah[a]);
            float uni   = wh + aw[a] * ah[a] - inter;
            float iou   = inter / (uni + 1e-16f);
            if (iou > bi) { bi = iou; best = a; }   // first max wins (strict >)
        }

        int b = idx / 24;
        s_key[idx]  = ((b * HH + gy) * WW + gx) * AA + best;
        s_t[idx][0] = cx * (float)WW - (float)gx;
        s_t[idx][1] = cy * (float)HH - (float)gy;
        s_t[idx][2] = logf(w / aw[best] + 1e-16f);
        s_t[idx][3] = logf(h / ah[best] + 1e-16f);
    }
    __syncthreads();

    float coord = 0.0f, objs = 0.0f, sppos = 0.0f;
    int npos = 0;

    for (int idx = tid; idx < NBOX; idx += THREADS) {
        int key = s_key[idx];
        if (key < 0) continue;
        // collisions only possible within the same batch; last scatter wins
        int bend = ((idx / 24) + 1) * 24;
        bool win = true;
        for (int j = idx + 1; j < bend; j++) {
            if (s_key[j] == key) { win = false; break; }
        }
        if (!win) continue;

        const float* p = pred + (long long)key * 5;
        float d0 = p[0] - s_t[idx][0];
        float d1 = p[1] - s_t[idx][1];
        float d2 = p[2] - s_t[idx][2];
        float d3 = p[3] - s_t[idx][3];
        coord += d0 * d0 + d1 * d1 + d2 * d2 + d3 * d3;
        float o = p[4];
        objs  += softplus_acc(-o);
        sppos += softplus_acc(o);
        npos++;
    }

    // reduce partials written by all blocks (fence+atomic chain makes them visible)
    float sall = 0.0f;
    for (int i = tid; i < BLOCKS; i += THREADS) sall += g_partials[i];

    __shared__ float r0s[THREADS], r1s[THREADS], r2s[THREADS], r3s[THREADS];
    __shared__ int   rns[THREADS];
    r0s[tid] = coord; r1s[tid] = objs; r2s[tid] = sppos; r3s[tid] = sall; rns[tid] = npos;
    __syncthreads();
    #pragma unroll
    for (int o = THREADS / 2; o > 0; o >>= 1) {
        if (tid < o) {
            r0s[tid] += r0s[tid + o];
            r1s[tid] += r1s[tid + o];
            r2s[tid] += r2s[tid + o];
            r3s[tid] += r3s[tid + o];
            rns[tid] += rns[tid + o];
        }
        __syncthreads();
    }

    if (tid == 0) {
        float np = (float)rns[0];
        float nn = (float)NCELL - np;
        float c  = 5.0f * r0s[0] / fmaxf(np, 1.0f);
        float ob = 1.0f * r1s[0] / fmaxf(np, 1.0f);
        float no = 0.5f * (r3s[0] - r2s[0]) / fmaxf(nn, 1.0f);
        out[0] = c + ob + no;
        out[1] = c;
        out[2] = ob;
        out[3] = no;
        out[4] = 0.0f;
        g_counter = 0;   // reset for next graph replay (deterministic)
    }
}

extern "C" void kernel_launch(void* const* d_in, const int* in_sizes, int n_in,
                              void* d_out, int out_size) {
    const float* pred = (const float*)d_in[0];
    const float* bbox = (const float*)d_in[1];
    float* out = (float*)d_out;
    (void)in_sizes; (void)n_in; (void)out_size;

    loss_kernel<<<BLOCKS, THREADS>>>(pred, bbox, out);
}